// round 1
// baseline (speedup 1.0000x reference)
#include <cuda_runtime.h>
#include <cuda_bf16.h>
#include <stdint.h>

#define BATCH 4
#define NPTS  64
#define DIM   128
#define NROWS (NPTS*NPTS)           // 4096 rows per batch
#define TILE  128
#define NT    (NROWS/TILE)          // 32 tiles per dim
#define NPAIR (NT*(NT+1)/2)         // 528 upper-triangle tile pairs
#define KCH   64                    // K chunk held in smem
#define LDS   72                    // padded smem row length (halves) -> conflict-free ldmatrix

// bf16 unit pairwise diffs: [tensor][b*NROWS + i*NPTS + j][d]
__device__ __nv_bfloat16 g_diff[2][(size_t)BATCH*NROWS*DIM];
__device__ double g_acc;

__global__ void zero_k() { g_acc = 0.0; }

// One warp per (tensor, b, i, j) row: diff, normalize in fp32, store bf16.
__global__ __launch_bounds__(256) void diff_k(const float* __restrict__ student,
                                              const float* __restrict__ teacher) {
    int warp = (blockIdx.x * blockDim.x + threadIdx.x) >> 5;
    int lane = threadIdx.x & 31;
    int tensor = warp >= BATCH * NROWS;
    int r = warp - tensor * BATCH * NROWS;     // 0 .. BATCH*NROWS-1
    int b = r / NROWS;
    int ij = r - b * NROWS;
    int i = ij / NPTS, j = ij - (ij / NPTS) * NPTS;
    const float* x = tensor ? teacher : student;
    const float4* xi = (const float4*)(x + (size_t)(b * NPTS + i) * DIM);
    const float4* xj = (const float4*)(x + (size_t)(b * NPTS + j) * DIM);
    float4 a = xi[lane], c = xj[lane];
    float d0 = a.x - c.x, d1 = a.y - c.y, d2 = a.z - c.z, d3 = a.w - c.w;
    float ss = d0*d0 + d1*d1 + d2*d2 + d3*d3;
    #pragma unroll
    for (int o = 16; o; o >>= 1) ss += __shfl_xor_sync(0xffffffffu, ss, o);
    float scale = 1.0f / fmaxf(sqrtf(ss), 1e-12f);   // zero rows stay zero
    __nv_bfloat162 p0 = __floats2bfloat162_rn(d0 * scale, d1 * scale);
    __nv_bfloat162 p1 = __floats2bfloat162_rn(d2 * scale, d3 * scale);
    __nv_bfloat162* out =
        (__nv_bfloat162*)(&g_diff[tensor][(size_t)r * DIM]) + lane * 2;
    out[0] = p0; out[1] = p1;
}

__device__ __forceinline__ void ldsm_x4(uint32_t* r, const void* p) {
    uint32_t addr = (uint32_t)__cvta_generic_to_shared(p);
    asm volatile("ldmatrix.sync.aligned.m8n8.x4.shared.b16 {%0,%1,%2,%3}, [%4];"
                 : "=r"(r[0]), "=r"(r[1]), "=r"(r[2]), "=r"(r[3]) : "r"(addr));
}

__device__ __forceinline__ void mma_bf16(float* c, const uint32_t* a, const uint32_t* b) {
    asm volatile(
        "mma.sync.aligned.m16n8k16.row.col.f32.bf16.bf16.f32 "
        "{%0,%1,%2,%3},{%4,%5,%6,%7},{%8,%9},{%0,%1,%2,%3};\n"
        : "+f"(c[0]), "+f"(c[1]), "+f"(c[2]), "+f"(c[3])
        : "r"(a[0]), "r"(a[1]), "r"(a[2]), "r"(a[3]), "r"(b[0]), "r"(b[1]));
}

// Fused Gram(student) / Gram(teacher) 128x128 tile + smooth-L1 reduction.
// blockIdx.x -> (batch, upper-triangle tile pair). Off-diagonal pairs weighted 2x.
__global__ __launch_bounds__(256) void gram_k() {
    int bid = blockIdx.x;
    int b = bid / NPAIR;
    int p = bid - b * NPAIR;
    int ti = 0, rem = p;
    while (rem >= NT - ti) { rem -= NT - ti; ti++; }
    int tj = ti + rem;

    __shared__ __align__(16) __nv_bfloat16 shA[TILE * LDS];
    __shared__ __align__(16) __nv_bfloat16 shB[TILE * LDS];
    __shared__ float wsum[8];

    int tid = threadIdx.x;
    int warp = tid >> 5, lane = tid & 31;
    int wm = warp & 3;        // 4 warps along M, 32 rows each
    int wn = warp >> 2;       // 2 warps along N, 64 cols each

    float accS[2][8][4], accT[2][8][4];
    #pragma unroll
    for (int f = 0; f < 2; f++)
        #pragma unroll
        for (int n = 0; n < 8; n++)
            #pragma unroll
            for (int e = 0; e < 4; e++) { accS[f][n][e] = 0.f; accT[f][n][e] = 0.f; }

    // ldmatrix lane addressing (precomputed pieces)
    int a_r = (lane & 7) + ((lane >> 3) & 1) * 8;     // A: row within 16
    int a_k = (lane >> 4) * 8;                        // A: k offset within 16
    int b_r = (lane & 7) + ((lane >> 4) & 1) * 8;     // B: row(n) within 16
    int b_k = ((lane >> 3) & 1) * 8;                  // B: k offset within 16

    #pragma unroll
    for (int mat = 0; mat < 2; mat++) {
        const __nv_bfloat16* gI = &g_diff[mat][((size_t)b * NROWS + ti * TILE) * DIM];
        const __nv_bfloat16* gJ = &g_diff[mat][((size_t)b * NROWS + tj * TILE) * DIM];
        float (*acc)[8][4] = mat ? accT : accS;

        #pragma unroll
        for (int kk = 0; kk < DIM; kk += KCH) {
            // Stage K-chunk: 128 rows x 64 halves per tile, int4 vectorized.
            #pragma unroll
            for (int u = 0; u < 4; u++) {
                int idx = tid + u * 256;          // 0..1023
                int row = idx >> 3, seg = idx & 7;
                *(int4*)(&shA[row * LDS + seg * 8]) =
                    *(const int4*)(gI + (size_t)row * DIM + kk + seg * 8);
                *(int4*)(&shB[row * LDS + seg * 8]) =
                    *(const int4*)(gJ + (size_t)row * DIM + kk + seg * 8);
            }
            __syncthreads();

            #pragma unroll
            for (int ks = 0; ks < KCH / 16; ks++) {
                uint32_t afr[2][4];
                uint32_t bfr[8][2];
                #pragma unroll
                for (int f = 0; f < 2; f++) {
                    int row = wm * 32 + f * 16 + a_r;
                    ldsm_x4(afr[f], &shA[row * LDS + ks * 16 + a_k]);
                }
                #pragma unroll
                for (int g = 0; g < 4; g++) {
                    int row = wn * 64 + g * 16 + b_r;
                    uint32_t t4[4];
                    ldsm_x4(t4, &shB[row * LDS + ks * 16 + b_k]);
                    bfr[2*g][0] = t4[0]; bfr[2*g][1] = t4[1];
                    bfr[2*g+1][0] = t4[2]; bfr[2*g+1][1] = t4[3];
                }
                #pragma unroll
                for (int f = 0; f < 2; f++)
                    #pragma unroll
                    for (int n = 0; n < 8; n++)
                        mma_bf16(acc[f][n], afr[f], bfr[n]);
            }
            __syncthreads();
        }
    }

    // Smooth-L1 epilogue + reduction
    float lsum = 0.f;
    #pragma unroll
    for (int f = 0; f < 2; f++)
        #pragma unroll
        for (int n = 0; n < 8; n++)
            #pragma unroll
            for (int e = 0; e < 4; e++) {
                float d = accS[f][n][e] - accT[f][n][e];
                float ad = fabsf(d);
                lsum += (ad < 1.0f) ? 0.5f * d * d : ad - 0.5f;
            }
    #pragma unroll
    for (int o = 16; o; o >>= 1) lsum += __shfl_xor_sync(0xffffffffu, lsum, o);
    if (lane == 0) wsum[warp] = lsum;
    __syncthreads();
    if (tid == 0) {
        float t = 0.f;
        #pragma unroll
        for (int w = 0; w < 8; w++) t += wsum[w];
        if (ti != tj) t *= 2.0f;
        atomicAdd(&g_acc, (double)t);
    }
}

__global__ void fin_k(float* out) {
    out[0] = (float)(g_acc / ((double)BATCH * NROWS * NROWS));
}

extern "C" void kernel_launch(void* const* d_in, const int* in_sizes, int n_in,
                              void* d_out, int out_size) {
    const float* student = (const float*)d_in[0];
    const float* teacher = (const float*)d_in[1];
    zero_k<<<1, 1>>>();
    diff_k<<<(2 * BATCH * NROWS) / 8, 256>>>(student, teacher);
    gram_k<<<BATCH * NPAIR, 256>>>();
    fin_k<<<1, 1>>>((float*)d_out);
}

// round 4
// speedup vs baseline: 1.2470x; 1.2470x over previous
#include <cuda_runtime.h>
#include <cuda_bf16.h>
#include <stdint.h>
#include <string.h>

#define BATCH  4
#define NPTS   64
#define DIM    128
#define NROWS  (NPTS*NPTS)        // 4096
#define KAUG   256                // augmented K: [sd | td]
#define TILE   128
#define NT     (NROWS/TILE)       // 32
#define NPAIR  (NT*(NT+1)/2)      // 528
#define GRID_G (BATCH*NPAIR)      // 2112
#define KCH    32                 // K-chunk (halves) per stage
#define NCHUNK (KAUG/KCH)         // 8
#define LDSH   40                 // padded smem row (halves): 80B, conflict-free
#define MATB   (TILE*LDSH*2)      // 10240 B per matrix per buffer
#define BUFB   (2*MATB)           // 20480 B per buffer (A+B)

__device__ __nv_bfloat16 g_X[(size_t)BATCH*NROWS*KAUG];  // [sd | td]
__device__ __nv_bfloat16 g_Y[(size_t)BATCH*NROWS*KAUG];  // [sd | -td]
__device__ double g_acc;
__device__ unsigned int g_done;

__device__ __forceinline__ uint32_t pack_bf2(float a, float b) {
    __nv_bfloat162 v = __floats2bfloat162_rn(a, b);
    uint32_t u; memcpy(&u, &v, 4); return u;
}

// ---------------------------------------------------------------- diff kernel
__global__ __launch_bounds__(256) void diff_k(const float* __restrict__ student,
                                              const float* __restrict__ teacher) {
    if (blockIdx.x == 0 && threadIdx.x == 0) { g_acc = 0.0; g_done = 0u; }
    int w = (blockIdx.x * blockDim.x + threadIdx.x) >> 5;
    int lane = threadIdx.x & 31;
    int b = w >> 12;
    int ij = w & 4095;
    int i = ij >> 6, j = ij & 63;

    const float4* si = (const float4*)(student + (size_t)(b*NPTS + i)*DIM);
    const float4* sj = (const float4*)(student + (size_t)(b*NPTS + j)*DIM);
    const float4* ti = (const float4*)(teacher + (size_t)(b*NPTS + i)*DIM);
    const float4* tj = (const float4*)(teacher + (size_t)(b*NPTS + j)*DIM);
    float4 a = si[lane], c = sj[lane], e = ti[lane], f = tj[lane];
    float s0 = a.x-c.x, s1 = a.y-c.y, s2 = a.z-c.z, s3 = a.w-c.w;
    float t0 = e.x-f.x, t1 = e.y-f.y, t2 = e.z-f.z, t3 = e.w-f.w;
    float ss = s0*s0+s1*s1+s2*s2+s3*s3;
    float st = t0*t0+t1*t1+t2*t2+t3*t3;
    #pragma unroll
    for (int o = 16; o; o >>= 1) {
        ss += __shfl_xor_sync(0xffffffffu, ss, o);
        st += __shfl_xor_sync(0xffffffffu, st, o);
    }
    float ks = 1.0f / fmaxf(sqrtf(ss), 1e-12f);
    float kt = 1.0f / fmaxf(sqrtf(st), 1e-12f);
    s0*=ks; s1*=ks; s2*=ks; s3*=ks;
    t0*=kt; t1*=kt; t2*=kt; t3*=kt;

    size_t r = (size_t)w * KAUG;
    uint2 sv, tv, tn;
    sv.x = pack_bf2(s0, s1);  sv.y = pack_bf2(s2, s3);
    tv.x = pack_bf2(t0, t1);  tv.y = pack_bf2(t2, t3);
    tn.x = pack_bf2(-t0, -t1); tn.y = pack_bf2(-t2, -t3);
    *(uint2*)(&g_X[r + lane*4])       = sv;
    *(uint2*)(&g_X[r + 128 + lane*4]) = tv;
    *(uint2*)(&g_Y[r + lane*4])       = sv;
    *(uint2*)(&g_Y[r + 128 + lane*4]) = tn;
}

// ---------------------------------------------------------------- mma helpers
__device__ __forceinline__ void ldsm_x4(uint32_t* r, const void* p) {
    uint32_t addr = (uint32_t)__cvta_generic_to_shared(p);
    asm volatile("ldmatrix.sync.aligned.m8n8.x4.shared.b16 {%0,%1,%2,%3}, [%4];"
                 : "=r"(r[0]), "=r"(r[1]), "=r"(r[2]), "=r"(r[3]) : "r"(addr));
}
__device__ __forceinline__ void mma_bf16(float* c, const uint32_t* a, const uint32_t* b) {
    asm volatile(
        "mma.sync.aligned.m16n8k16.row.col.f32.bf16.bf16.f32 "
        "{%0,%1,%2,%3},{%4,%5,%6,%7},{%8,%9},{%0,%1,%2,%3};\n"
        : "+f"(c[0]), "+f"(c[1]), "+f"(c[2]), "+f"(c[3])
        : "r"(a[0]), "r"(a[1]), "r"(a[2]), "r"(a[3]), "r"(b[0]), "r"(b[1]));
}
__device__ __forceinline__ void cp16(void* dst, const void* src) {
    uint32_t d = (uint32_t)__cvta_generic_to_shared(dst);
    asm volatile("cp.async.cg.shared.global [%0], [%1], 16;" :: "r"(d), "l"(src));
}
#define CP_COMMIT() asm volatile("cp.async.commit_group;" ::: "memory")
#define CP_WAIT1()  asm volatile("cp.async.wait_group 1;" ::: "memory")
#define CP_WAIT0()  asm volatile("cp.async.wait_group 0;" ::: "memory")

// ---------------------------------------------------------------- gram kernel
// One CTA = (batch, upper-tri 128x128 tile pair). D = X_I · Y_J^T, K=256,
// cp.async double-buffered K-chunks of 32 halves. Smooth-L1 epilogue on regs,
// last CTA writes the final mean.
__global__ __launch_bounds__(256, 2) void gram_k(float* __restrict__ out) {
    __shared__ __align__(16) char smem[2 * BUFB];
    __shared__ float wsum[8];

    int tid = threadIdx.x, wid = tid >> 5, lane = tid & 31;
    int bid = blockIdx.x;
    int b = bid / NPAIR;
    int p = bid - b * NPAIR;
    int ti_ = 0, rem = p;
    while (rem >= NT - ti_) { rem -= NT - ti_; ti_++; }
    int tj_ = ti_ + rem;

    const __nv_bfloat16* gI = g_X + ((size_t)b * NROWS + (size_t)ti_ * TILE) * KAUG;
    const __nv_bfloat16* gJ = g_Y + ((size_t)b * NROWS + (size_t)tj_ * TILE) * KAUG;

    int wm = wid & 3;   // 4 warps along M (32 rows each)
    int wn = wid >> 2;  // 2 warps along N (64 cols each)

    float acc[2][8][4];
    #pragma unroll
    for (int f = 0; f < 2; f++)
        #pragma unroll
        for (int n = 0; n < 8; n++)
            #pragma unroll
            for (int e = 0; e < 4; e++) acc[f][n][e] = 0.f;

    int a_r = (lane & 7) + ((lane >> 3) & 1) * 8;
    int a_k = (lane >> 4) * 8;
    int b_r = (lane & 7) + ((lane >> 4) & 1) * 8;
    int b_k = ((lane >> 3) & 1) * 8;

    // chunk loader: per matrix 128 rows x 32 halves (64B = 4 int4 per row)
    int l_row = tid >> 2, l_seg = tid & 3;           // 64 rows per 256-thread pass? no:
    // idx = tid + u*256 ; row = idx>>2 (0..127), seg = idx&3
    auto load_chunk = [&](int c) {
        char* buf = smem + (c & 1) * BUFB;
        #pragma unroll
        for (int u = 0; u < 2; u++) {
            int idx = tid + u * 256;
            int row = idx >> 2, seg = idx & 3;
            size_t goff = (size_t)row * KAUG + c * KCH + seg * 8;
            char* d = buf + row * (LDSH * 2) + seg * 16;
            cp16(d, gI + goff);
            cp16(d + MATB, gJ + goff);
        }
        CP_COMMIT();
    };

    load_chunk(0);

    #pragma unroll
    for (int c = 0; c < NCHUNK; c++) {
        if (c + 1 < NCHUNK) { load_chunk(c + 1); CP_WAIT1(); }
        else CP_WAIT0();
        __syncthreads();

        const __nv_bfloat16* shA = (const __nv_bfloat16*)(smem + (c & 1) * BUFB);
        const __nv_bfloat16* shB = (const __nv_bfloat16*)(smem + (c & 1) * BUFB + MATB);
        #pragma unroll
        for (int ks = 0; ks < KCH / 16; ks++) {
            uint32_t afr[2][4];
            uint32_t bfr[8][2];
            #pragma unroll
            for (int f = 0; f < 2; f++) {
                int row = wm * 32 + f * 16 + a_r;
                ldsm_x4(afr[f], &shA[row * LDSH + ks * 16 + a_k]);
            }
            #pragma unroll
            for (int g = 0; g < 4; g++) {
                int row = wn * 64 + g * 16 + b_r;
                uint32_t t4[4];
                ldsm_x4(t4, &shB[row * LDSH + ks * 16 + b_k]);
                bfr[2*g][0] = t4[0]; bfr[2*g][1] = t4[1];
                bfr[2*g+1][0] = t4[2]; bfr[2*g+1][1] = t4[3];
            }
            #pragma unroll
            for (int f = 0; f < 2; f++)
                #pragma unroll
                for (int n = 0; n < 8; n++)
                    mma_bf16(acc[f][n], afr[f], bfr[n]);
        }
        __syncthreads();
    }

    // smooth-L1 epilogue + block reduction
    float lsum = 0.f;
    #pragma unroll
    for (int f = 0; f < 2; f++)
        #pragma unroll
        for (int n = 0; n < 8; n++)
            #pragma unroll
            for (int e = 0; e < 4; e++) {
                float d = acc[f][n][e];
                float ad = fabsf(d);
                lsum += (ad < 1.0f) ? 0.5f * d * d : ad - 0.5f;
            }
    #pragma unroll
    for (int o = 16; o; o >>= 1) lsum += __shfl_xor_sync(0xffffffffu, lsum, o);
    if (lane == 0) wsum[wid] = lsum;
    __syncthreads();
    if (tid == 0) {
        float t = 0.f;
        #pragma unroll
        for (int w = 0; w < 8; w++) t += wsum[w];
        if (ti_ != tj_) t *= 2.0f;
        atomicAdd(&g_acc, (double)t);
        __threadfence();
        unsigned int ticket = atomicAdd(&g_done, 1u);
        if (ticket == GRID_G - 1) {
            double v = *((volatile double*)&g_acc);
            out[0] = (float)(v / ((double)BATCH * NROWS * NROWS));
        }
    }
}

extern "C" void kernel_launch(void* const* d_in, const int* in_sizes, int n_in,
                              void* d_out, int out_size) {
    const float* student = (const float*)d_in[0];
    const float* teacher = (const float*)d_in[1];
    diff_k<<<(BATCH * NROWS) / 8, 256>>>(student, teacher);
    gram_k<<<GRID_G, 256>>>((float*)d_out);
}